// round 16
// baseline (speedup 1.0000x reference)
#include <cuda_runtime.h>
#include <math.h>
#include <stdint.h>

// Problem constants (shapes fixed by the dataset)
#define B_    4
#define S0    12          // token_init side; compact row count per batch = 144
#define M144  144         // unique rows per batch
#define MT    576         // B_*M144
#define DIM   256
#define NP    128         // nPnt
#define HID   512         // 4*nPnt
#define H_    120
#define W_    160

typedef unsigned long long ull;

// ---------------- scratch (device globals) ------------------------------------
__device__ float g_A0   [MT * NP];             // compact t @ P^T / 16   [576,128]
__device__ float g_H    [MT * 2 * HID];        // hidden, nr [0,512) na [512,1024)
__device__ float g_padj [2 * MT * NP];         // fc2 nr partials (split-K halves)
__device__ float g_pattn[2 * MT * NP];         // fc2 na partials
__device__ float g_fus  [B_ * NP * DIM];       // token_fused [4,128,256]
__device__ float g_U    [MT * DIM];            // unique output rows [576,256]

__device__ __forceinline__ float gelu_exact(float x) {
    return 0.5f * x * (1.0f + erff(x * 0.70710678118654752440f));
}

// ===================== templated fp32 GEMM (R4-proven + split-K) ==============
template<int BM, int BN, int BK, int TM, int TN,
         bool TRANSB, bool ACT, bool BIAS, bool RESID, bool DUAL, int SPLITK>
__global__ __launch_bounds__((BM / TM) * (BN / TN))
void gemm_f32(const float* __restrict__ A,
              const float* __restrict__ B0, const float* __restrict__ B1,
              const float* __restrict__ bias0, const float* __restrict__ bias1,
              const float* __restrict__ R,
              float* __restrict__ C0, float* __restrict__ C1,
              int K, float alpha,
              long sA, int lda, int ofsA,
              long sB, int ldb,
              long sC, int ldc, int ofsC,
              long sR, int ldr, long sPart)
{
    constexpr int THREADS = (BM / TM) * (BN / TN);
    constexpr int NA = (BM * BK) / THREADS;
    constexpr int NB = (BN * BK) / THREADS;
    static_assert(NA * THREADS == BM * BK, "A load divisibility");
    static_assert(NB * THREADS == BN * BK, "B load divisibility");

#if __CUDA_ARCH__ >= 900
    cudaGridDependencySynchronize();
#endif

    const int z  = blockIdx.z;
    const int kc = (SPLITK > 1) ? (z % SPLITK) : 0;
    const int r2 = (SPLITK > 1) ? (z / SPLITK) : z;
    const int br = DUAL ? (r2 & 1) : 0;
    const int bz = DUAL ? (r2 >> 1) : r2;

    const int Kc = K / SPLITK;

    const float* Bw  = (DUAL && br) ? B1 : B0;
    const float* bia = (DUAL && br) ? bias1 : bias0;
    float*       C   = (DUAL && br) ? C1 : C0;

    A  += (long)bz * sA + (long)br * ofsA + (long)kc * Kc;
    Bw += (long)bz * sB + (TRANSB ? (long)kc * Kc : (long)kc * Kc * ldb);
    C  += (long)bz * sC + (long)br * ofsC + (long)kc * sPart;
    const float* Rp = R + (long)bz * sR;

    __shared__ float As[BK][BM + 1];
    __shared__ float Bs[BK][BN + 1];

    const int tid  = threadIdx.x;
    const int row0 = blockIdx.y * BM;
    const int col0 = blockIdx.x * BN;
    const int tn   = tid % (BN / TN);
    const int tm   = tid / (BN / TN);
    const int m0   = tm * TM;
    const int n0   = tn * TN;

    float acc[TM][TN];
#pragma unroll
    for (int i = 0; i < TM; i++)
#pragma unroll
        for (int j = 0; j < TN; j++) acc[i][j] = 0.f;

    float regA[NA], regB[NB];
    const int nT = Kc / BK;

#pragma unroll
    for (int j = 0; j < NA; j++) {
        int idx = tid + j * THREADS;
        int r = idx / BK, k = idx % BK;
        regA[j] = A[(long)(row0 + r) * lda + k];
    }
#pragma unroll
    for (int j = 0; j < NB; j++) {
        int idx = tid + j * THREADS;
        if (TRANSB) { int n = idx / BK, k = idx % BK; regB[j] = Bw[(long)(col0 + n) * ldb + k]; }
        else        { int k = idx / BN, n = idx % BN; regB[j] = Bw[(long)k * ldb + col0 + n]; }
    }

    for (int t = 0; t < nT; t++) {
#pragma unroll
        for (int j = 0; j < NA; j++) {
            int idx = tid + j * THREADS;
            int r = idx / BK, k = idx % BK;
            As[k][r] = regA[j];
        }
#pragma unroll
        for (int j = 0; j < NB; j++) {
            int idx = tid + j * THREADS;
            if (TRANSB) { int n = idx / BK, k = idx % BK; Bs[k][n] = regB[j]; }
            else        { int k = idx / BN, n = idx % BN; Bs[k][n] = regB[j]; }
        }
        __syncthreads();

        if (t + 1 < nT) {
            const int k0 = (t + 1) * BK;
#pragma unroll
            for (int j = 0; j < NA; j++) {
                int idx = tid + j * THREADS;
                int r = idx / BK, k = idx % BK;
                regA[j] = A[(long)(row0 + r) * lda + k0 + k];
            }
#pragma unroll
            for (int j = 0; j < NB; j++) {
                int idx = tid + j * THREADS;
                if (TRANSB) { int n = idx / BK, k = idx % BK; regB[j] = Bw[(long)(col0 + n) * ldb + k0 + k]; }
                else        { int k = idx / BN, n = idx % BN; regB[j] = Bw[(long)(k0 + k) * ldb + col0 + n]; }
            }
        }

#pragma unroll
        for (int kk = 0; kk < BK; kk++) {
            float av[TM], bv[TN];
#pragma unroll
            for (int i = 0; i < TM; i++) av[i] = As[kk][m0 + i];
#pragma unroll
            for (int j = 0; j < TN; j++) bv[j] = Bs[kk][n0 + j];
#pragma unroll
            for (int i = 0; i < TM; i++)
#pragma unroll
                for (int j = 0; j < TN; j++)
                    acc[i][j] += av[i] * bv[j];
        }
        __syncthreads();
    }

    float bf[TN];
#pragma unroll
    for (int j = 0; j < TN; j++) bf[j] = BIAS ? bia[col0 + n0 + j] : 0.f;
#pragma unroll
    for (int i = 0; i < TM; i++) {
        const int row = row0 + m0 + i;
#pragma unroll
        for (int j = 0; j < TN; j++) {
            float v = acc[i][j] * alpha + bf[j];
            if (ACT)   v = gelu_exact(v);
            if (RESID) v += Rp[(long)row * ldr + col0 + n0 + j];
            C[(long)row * ldc + col0 + n0 + j] = v;
        }
    }
}

// ---------------- fused node contraction + token_fused MLP (ILP version) ------
// grid (NP, B_, 2) = 1024 blocks, 128 threads; thread = ONE scalar d.
// fc1 inverted to i-outer / j-inner with 48 independent accumulators (no RAW
// chains); gelu phase is 48 independent evals with 4 interleaved output chains.
__global__ __launch_bounds__(128)
void node_tf_fused(const float* __restrict__ t,        // token_init [4,144,256]
                   const float* __restrict__ nr_b2,
                   const float* __restrict__ w1, const float* __restrict__ b1,
                   const float* __restrict__ w2, const float* __restrict__ b2,
                   float rs2)
{
#if __CUDA_ARCH__ >= 900
    cudaGridDependencySynchronize();
#endif
    __shared__ __align__(16) float adjc[M144];         // a*rs2
    __shared__ __align__(16) float w1i[24][48];        // folded w1, i-major
    __shared__ float b1s[48];
    __shared__ float w2s[48];

    const int p   = blockIdx.x;        // 0..127
    const int b   = blockIdx.y;        // 0..3
    const int dh  = blockIdx.z;        // 0..1 (d-half)
    const int tid = threadIdx.x;       // 0..127

    // combined adj column (fc2 split-K + bias), rs2 folded in
    {
        long i0 = (long)(b * M144 + tid) * NP + p;
        adjc[tid] = (g_padj[i0] + g_padj[(long)MT * NP + i0] + nr_b2[p]) * rs2;
        if (tid < M144 - 128) {
            const int m2 = 128 + tid;
            long i1 = (long)(b * M144 + m2) * NP + p;
            adjc[m2] = (g_padj[i1] + g_padj[(long)MT * NP + i1] + nr_b2[p]) * rs2;
        }
    }
    // folded w1, i-major: w1i[i][j] = w1[2i][j] + w1[2i+1][j]
    for (int idx = tid; idx < 24 * 48; idx += 128) {
        int i = idx / 48, j = idx % 48;
        w1i[i][j] = w1[(2 * i) * 48 + j] + w1[(2 * i + 1) * 48 + j];
    }
    if (tid < 48) { b1s[tid] = b1[tid]; w2s[tid] = w2[tid]; }
    __syncthreads();

    const int d = dh * 128 + tid;
    const float* tb = t + ((long)b * M144) * DIM + d;

    // contraction: x[h] and x[12+w] accumulate a*t over the 12x12 grid
    float x[24];
#pragma unroll
    for (int i = 0; i < 24; i++) x[i] = 0.f;

#pragma unroll
    for (int h = 0; h < S0; h++) {
#pragma unroll
        for (int w = 0; w < S0; w++) {
            const int r = h * S0 + w;
            float v = adjc[r] * tb[(long)r * DIM];
            x[h]      += v;
            x[12 + w] += v;
        }
    }

    // fc1: i-outer / j-inner, 48 independent accumulators (full FMA ILP)
    float a[48];
#pragma unroll
    for (int j = 0; j < 48; j++) a[j] = b1s[j];

#pragma unroll
    for (int i = 0; i < 24; i++) {
        const float xv = x[i];
        const float4* wr = (const float4*)&w1i[i][0];
#pragma unroll
        for (int j4 = 0; j4 < 12; j4++) {
            float4 w = wr[j4];
            a[j4 * 4 + 0] += xv * w.x;
            a[j4 * 4 + 1] += xv * w.y;
            a[j4 * 4 + 2] += xv * w.z;
            a[j4 * 4 + 3] += xv * w.w;
        }
    }

    // gelu + fc2 dot: 48 independent gelus, 4 interleaved output chains
    float o0 = 0.f, o1 = 0.f, o2 = 0.f, o3 = 0.f;
#pragma unroll
    for (int j = 0; j < 48; j += 4) {
        o0 += gelu_exact(a[j + 0]) * w2s[j + 0];
        o1 += gelu_exact(a[j + 1]) * w2s[j + 1];
        o2 += gelu_exact(a[j + 2]) * w2s[j + 2];
        o3 += gelu_exact(a[j + 3]) * w2s[j + 3];
    }
    g_fus[((long)(b * NP) + p) * DIM + d] = ((b2[0] + o0) + o1) + (o2 + o3);
}

// ---------------- U = softmax(fc2_na) @ fus + t, softmax fused ----------------
__global__ __launch_bounds__(128)
void u_softmax_gemm(const float* __restrict__ na_b2,
                    const float* __restrict__ t)
{
#if __CUDA_ARCH__ >= 900
    cudaGridDependencySynchronize();
#endif
    __shared__ float As[NP][17];        // softmaxed attn, [k][row]
    __shared__ __align__(16) float Bs[NP][68];   // fus panel [k][col]

    const int cb  = blockIdx.x;
    const int rb  = blockIdx.y;
    const int b   = blockIdx.z;
    const int tid = threadIdx.x;
    const int row0 = rb * 16;
    const int col0 = cb * 64;

    {
        const float* fb = g_fus + ((long)b * NP) * DIM + col0;
        for (int idx = tid; idx < NP * 16; idx += 128) {
            int k = idx >> 4, c4 = (idx & 15) * 4;
            float4 v = *(const float4*)&fb[(long)k * DIM + c4];
            *(float4*)&Bs[k][c4] = v;
        }
    }

    {
        const int lr  = tid >> 3;
        const int sub = tid & 7;
        const long rbase = ((long)(b * M144) + row0 + lr) * NP;
        float v[16];
        float mx = -1e30f;
#pragma unroll
        for (int i = 0; i < 16; i++) {
            int k = sub * 16 + i;
            v[i] = g_pattn[rbase + k] + g_pattn[(long)MT * NP + rbase + k] + na_b2[k];
            mx = fmaxf(mx, v[i]);
        }
#pragma unroll
        for (int o = 1; o < 8; o <<= 1) mx = fmaxf(mx, __shfl_xor_sync(0xffffffffu, mx, o));
        float sum = 0.f;
#pragma unroll
        for (int i = 0; i < 16; i++) { v[i] = expf(v[i] - mx); sum += v[i]; }
#pragma unroll
        for (int o = 1; o < 8; o <<= 1) sum += __shfl_xor_sync(0xffffffffu, sum, o);
        float inv = 1.f / sum;
#pragma unroll
        for (int i = 0; i < 16; i++) As[sub * 16 + i][lr] = v[i] * inv;
    }
    __syncthreads();

    const int tm = tid >> 4;
    const int tn = tid & 15;
    const int m0 = tm * 2;
    const int n0 = tn * 4;

    float acc[2][4];
#pragma unroll
    for (int i = 0; i < 2; i++)
#pragma unroll
        for (int j = 0; j < 4; j++) acc[i][j] = 0.f;

#pragma unroll 8
    for (int k = 0; k < NP; k++) {
        float a0 = As[k][m0], a1 = As[k][m0 + 1];
        float4 bb = *(const float4*)&Bs[k][n0];
        acc[0][0] += a0 * bb.x; acc[0][1] += a0 * bb.y;
        acc[0][2] += a0 * bb.z; acc[0][3] += a0 * bb.w;
        acc[1][0] += a1 * bb.x; acc[1][1] += a1 * bb.y;
        acc[1][2] += a1 * bb.z; acc[1][3] += a1 * bb.w;
    }

#pragma unroll
    for (int i = 0; i < 2; i++) {
        const int row = row0 + m0 + i;
        const float4 r = *(const float4*)&t[((long)(b * M144) + row) * DIM + col0 + n0];
        float4 v;
        v.x = acc[i][0] + r.x; v.y = acc[i][1] + r.y;
        v.z = acc[i][2] + r.z; v.w = acc[i][3] + r.w;
        *(float4*)&g_U[((long)(b * M144) + row) * DIM + col0 + n0] = v;
    }
}

// ---------------- final scatter-broadcast of the 144 unique rows --------------
__global__ __launch_bounds__(256)
void scatter_kernel(float4* __restrict__ out) {
#if __CUDA_ARCH__ >= 900
    cudaGridDependencySynchronize();
#endif
    const int wq = threadIdx.x >> 6;
    const int dq = threadIdx.x & 63;
    const int w  = blockIdx.x * 4 + wq;
    const int h  = blockIdx.y;
    const int b  = blockIdx.z;
    const int r  = (h / 10) * S0 + (3 * w) / 40;
    const float4* src = reinterpret_cast<const float4*>(g_U)
                        + (long)(b * M144 + r) * (DIM / 4);
    float4* dst = out + (long)(((b * H_) + h) * W_ + w) * (DIM / 4);
    dst[dq] = src[dq];
}

// ---------------- PDL launch helper -------------------------------------------
template<typename K, typename... A>
static void launch_pdl(dim3 g, dim3 blk, K kern, A... args) {
    cudaLaunchConfig_t cfg = {};
    cfg.gridDim = g;
    cfg.blockDim = blk;
    cfg.dynamicSmemBytes = 0;
    cfg.stream = 0;
    cudaLaunchAttribute at;
    at.id = cudaLaunchAttributeProgrammaticStreamSerialization;
    at.val.programmaticStreamSerializationAllowed = 1;
    cfg.attrs = &at;
    cfg.numAttrs = 1;
    cudaLaunchKernelEx(&cfg, kern, args...);
}

// ==============================================================================
extern "C" void kernel_launch(void* const* d_in, const int* in_sizes, int n_in,
                              void* d_out, int out_size) {
    const float* token_init  = (const float*)d_in[0];   // [4,12,12,256] == compact t
    const float* point_token = (const float*)d_in[1];
    const float* nr_w1 = (const float*)d_in[2];
    const float* nr_b1 = (const float*)d_in[3];
    const float* nr_w2 = (const float*)d_in[4];
    const float* nr_b2 = (const float*)d_in[5];
    const float* na_w1 = (const float*)d_in[6];
    const float* na_b1 = (const float*)d_in[7];
    const float* na_w2 = (const float*)d_in[8];
    const float* na_b2 = (const float*)d_in[9];
    const float* tf_w1 = (const float*)d_in[10];
    const float* tf_b1 = (const float*)d_in[11];
    const float* tf_w2 = (const float*)d_in[12];
    const float* tf_b2 = (const float*)d_in[13];
    float* out = (float*)d_out;

    float *A0_p, *H_p, *padj_p, *pattn_p;
    cudaGetSymbolAddress((void**)&A0_p,   g_A0);
    cudaGetSymbolAddress((void**)&H_p,    g_H);
    cudaGetSymbolAddress((void**)&padj_p, g_padj);
    cudaGetSymbolAddress((void**)&pattn_p,g_pattn);

    const float scale = 0.0625f;                    // dim^-0.5
    const float rs2   = 2.f * 0.20412414523193154f; // 2 * 24^-0.5

    // 1. A0 = t144 @ P^T * scale   [4*144,128]
    launch_pdl(dim3(NP / 32, M144 / 16, B_), dim3(64),
        gemm_f32<16, 32, 16, 2, 4, true, false, false, false, false, 1>,
        token_init, point_token, (const float*)nullptr,
        (const float*)nullptr, (const float*)nullptr, (const float*)nullptr,
        A0_p, (float*)nullptr,
        (int)DIM, scale,
        (long)M144 * DIM, (int)DIM, 0,
        (long)NP * DIM, (int)DIM,
        (long)M144 * NP, (int)NP, 0,
        (long)0, 0, (long)0);

    // 2. fc1 (nr & na): H = gelu(A0 @ w1 + b1)   [576,1024]
    launch_pdl(dim3(HID / 64, MT / 32, 2), dim3(128),
        gemm_f32<32, 64, 16, 4, 4, false, true, true, false, true, 1>,
        (const float*)A0_p, nr_w1, na_w1, nr_b1, na_b1, (const float*)nullptr,
        H_p, H_p,
        (int)NP, 1.f,
        (long)0, (int)NP, 0,
        (long)0, (int)HID,
        (long)0, (int)(2 * HID), (int)HID,
        (long)0, 0, (long)0);

    // 3. fc2 split-K2 (nr & na): raw partials (bias added by consumers)
    launch_pdl(dim3(NP / 32, MT / 32, 4), dim3(128),
        gemm_f32<32, 32, 16, 4, 2, false, false, false, false, true, 2>,
        (const float*)H_p, nr_w2, na_w2,
        (const float*)nullptr, (const float*)nullptr, (const float*)nullptr,
        padj_p, pattn_p,
        (int)HID, 1.f,
        (long)0, (int)(2 * HID), (int)HID,
        (long)0, (int)NP,
        (long)0, (int)NP, 0,
        (long)0, 0, (long)MT * NP);

    // 4. fused node contraction + token_fused MLP (ILP-restructured, d-split)
    launch_pdl(dim3(NP, B_, 2), dim3(128),
        node_tf_fused,
        token_init, nr_b2, tf_w1, tf_b1, tf_w2, tf_b2, rs2);

    // 5. U = softmax(na partials + bias) @ fus + t144   [4*144,256]
    launch_pdl(dim3(DIM / 64, M144 / 16, B_), dim3(128),
        u_softmax_gemm, na_b2, token_init);

    // 6. broadcast unique rows to the full [4,19200,256] output
    launch_pdl(dim3(W_ / 4, H_, B_), dim3(256),
        scatter_kernel, (float4*)out);
}

// round 17
// speedup vs baseline: 1.0112x; 1.0112x over previous
#include <cuda_runtime.h>
#include <math.h>
#include <stdint.h>

// Problem constants (shapes fixed by the dataset)
#define B_    4
#define S0    12          // token_init side; compact row count per batch = 144
#define M144  144         // unique rows per batch
#define MT    576         // B_*M144
#define DIM   256
#define NP    128         // nPnt
#define HID   512         // 4*nPnt
#define H_    120
#define W_    160

typedef unsigned long long ull;

// ---------------- scratch (device globals) ------------------------------------
__device__ float g_A0   [MT * NP];             // compact t @ P^T / 16   [576,128]
__device__ float g_H    [MT * 2 * HID];        // hidden, nr [0,512) na [512,1024)
__device__ float g_padj [2 * MT * NP];         // fc2 nr partials (split-K halves)
__device__ float g_pattn[2 * MT * NP];         // fc2 na partials
__device__ float g_fus  [B_ * NP * DIM];       // token_fused [4,128,256]
__device__ float g_U    [MT * DIM];            // unique output rows [576,256]

__device__ __forceinline__ float gelu_exact(float x) {
    return 0.5f * x * (1.0f + erff(x * 0.70710678118654752440f));
}

// ===================== templated fp32 GEMM (R4-proven + split-K) ==============
template<int BM, int BN, int BK, int TM, int TN,
         bool TRANSB, bool ACT, bool BIAS, bool RESID, bool DUAL, int SPLITK>
__global__ __launch_bounds__((BM / TM) * (BN / TN))
void gemm_f32(const float* __restrict__ A,
              const float* __restrict__ B0, const float* __restrict__ B1,
              const float* __restrict__ bias0, const float* __restrict__ bias1,
              const float* __restrict__ R,
              float* __restrict__ C0, float* __restrict__ C1,
              int K, float alpha,
              long sA, int lda, int ofsA,
              long sB, int ldb,
              long sC, int ldc, int ofsC,
              long sR, int ldr, long sPart)
{
    constexpr int THREADS = (BM / TM) * (BN / TN);
    constexpr int NA = (BM * BK) / THREADS;
    constexpr int NB = (BN * BK) / THREADS;
    static_assert(NA * THREADS == BM * BK, "A load divisibility");
    static_assert(NB * THREADS == BN * BK, "B load divisibility");

#if __CUDA_ARCH__ >= 900
    cudaGridDependencySynchronize();
#endif

    const int z  = blockIdx.z;
    const int kc = (SPLITK > 1) ? (z % SPLITK) : 0;
    const int r2 = (SPLITK > 1) ? (z / SPLITK) : z;
    const int br = DUAL ? (r2 & 1) : 0;
    const int bz = DUAL ? (r2 >> 1) : r2;

    const int Kc = K / SPLITK;

    const float* Bw  = (DUAL && br) ? B1 : B0;
    const float* bia = (DUAL && br) ? bias1 : bias0;
    float*       C   = (DUAL && br) ? C1 : C0;

    A  += (long)bz * sA + (long)br * ofsA + (long)kc * Kc;
    Bw += (long)bz * sB + (TRANSB ? (long)kc * Kc : (long)kc * Kc * ldb);
    C  += (long)bz * sC + (long)br * ofsC + (long)kc * sPart;
    const float* Rp = R + (long)bz * sR;

    __shared__ float As[BK][BM + 1];
    __shared__ float Bs[BK][BN + 1];

    const int tid  = threadIdx.x;
    const int row0 = blockIdx.y * BM;
    const int col0 = blockIdx.x * BN;
    const int tn   = tid % (BN / TN);
    const int tm   = tid / (BN / TN);
    const int m0   = tm * TM;
    const int n0   = tn * TN;

    float acc[TM][TN];
#pragma unroll
    for (int i = 0; i < TM; i++)
#pragma unroll
        for (int j = 0; j < TN; j++) acc[i][j] = 0.f;

    float regA[NA], regB[NB];
    const int nT = Kc / BK;

#pragma unroll
    for (int j = 0; j < NA; j++) {
        int idx = tid + j * THREADS;
        int r = idx / BK, k = idx % BK;
        regA[j] = A[(long)(row0 + r) * lda + k];
    }
#pragma unroll
    for (int j = 0; j < NB; j++) {
        int idx = tid + j * THREADS;
        if (TRANSB) { int n = idx / BK, k = idx % BK; regB[j] = Bw[(long)(col0 + n) * ldb + k]; }
        else        { int k = idx / BN, n = idx % BN; regB[j] = Bw[(long)k * ldb + col0 + n]; }
    }

    for (int t = 0; t < nT; t++) {
#pragma unroll
        for (int j = 0; j < NA; j++) {
            int idx = tid + j * THREADS;
            int r = idx / BK, k = idx % BK;
            As[k][r] = regA[j];
        }
#pragma unroll
        for (int j = 0; j < NB; j++) {
            int idx = tid + j * THREADS;
            if (TRANSB) { int n = idx / BK, k = idx % BK; Bs[k][n] = regB[j]; }
            else        { int k = idx / BN, n = idx % BN; Bs[k][n] = regB[j]; }
        }
        __syncthreads();

        if (t + 1 < nT) {
            const int k0 = (t + 1) * BK;
#pragma unroll
            for (int j = 0; j < NA; j++) {
                int idx = tid + j * THREADS;
                int r = idx / BK, k = idx % BK;
                regA[j] = A[(long)(row0 + r) * lda + k0 + k];
            }
#pragma unroll
            for (int j = 0; j < NB; j++) {
                int idx = tid + j * THREADS;
                if (TRANSB) { int n = idx / BK, k = idx % BK; regB[j] = Bw[(long)(col0 + n) * ldb + k0 + k]; }
                else        { int k = idx / BN, n = idx % BN; regB[j] = Bw[(long)(k0 + k) * ldb + col0 + n]; }
            }
        }

#pragma unroll
        for (int kk = 0; kk < BK; kk++) {
            float av[TM], bv[TN];
#pragma unroll
            for (int i = 0; i < TM; i++) av[i] = As[kk][m0 + i];
#pragma unroll
            for (int j = 0; j < TN; j++) bv[j] = Bs[kk][n0 + j];
#pragma unroll
            for (int i = 0; i < TM; i++)
#pragma unroll
                for (int j = 0; j < TN; j++)
                    acc[i][j] += av[i] * bv[j];
        }
        __syncthreads();
    }

    float bf[TN];
#pragma unroll
    for (int j = 0; j < TN; j++) bf[j] = BIAS ? bia[col0 + n0 + j] : 0.f;
#pragma unroll
    for (int i = 0; i < TM; i++) {
        const int row = row0 + m0 + i;
#pragma unroll
        for (int j = 0; j < TN; j++) {
            float v = acc[i][j] * alpha + bf[j];
            if (ACT)   v = gelu_exact(v);
            if (RESID) v += Rp[(long)row * ldr + col0 + n0 + j];
            C[(long)row * ldc + col0 + n0 + j] = v;
        }
    }
}

// ---------------- fused node contraction + token_fused MLP (ILP version) ------
// grid (NP, B_, 2) = 1024 blocks, 128 threads; thread = ONE scalar d.
// fc1 inverted to i-outer / j-inner with 48 independent accumulators (no RAW
// chains); gelu phase is 48 independent evals with 4 interleaved output chains.
__global__ __launch_bounds__(128)
void node_tf_fused(const float* __restrict__ t,        // token_init [4,144,256]
                   const float* __restrict__ nr_b2,
                   const float* __restrict__ w1, const float* __restrict__ b1,
                   const float* __restrict__ w2, const float* __restrict__ b2,
                   float rs2)
{
#if __CUDA_ARCH__ >= 900
    cudaGridDependencySynchronize();
#endif
    __shared__ __align__(16) float adjc[M144];         // a*rs2
    __shared__ __align__(16) float w1i[24][48];        // folded w1, i-major
    __shared__ float b1s[48];
    __shared__ float w2s[48];

    const int p   = blockIdx.x;        // 0..127
    const int b   = blockIdx.y;        // 0..3
    const int dh  = blockIdx.z;        // 0..1 (d-half)
    const int tid = threadIdx.x;       // 0..127

    // combined adj column (fc2 split-K + bias), rs2 folded in
    {
        long i0 = (long)(b * M144 + tid) * NP + p;
        adjc[tid] = (g_padj[i0] + g_padj[(long)MT * NP + i0] + nr_b2[p]) * rs2;
        if (tid < M144 - 128) {
            const int m2 = 128 + tid;
            long i1 = (long)(b * M144 + m2) * NP + p;
            adjc[m2] = (g_padj[i1] + g_padj[(long)MT * NP + i1] + nr_b2[p]) * rs2;
        }
    }
    // folded w1, i-major: w1i[i][j] = w1[2i][j] + w1[2i+1][j]
    for (int idx = tid; idx < 24 * 48; idx += 128) {
        int i = idx / 48, j = idx % 48;
        w1i[i][j] = w1[(2 * i) * 48 + j] + w1[(2 * i + 1) * 48 + j];
    }
    if (tid < 48) { b1s[tid] = b1[tid]; w2s[tid] = w2[tid]; }
    __syncthreads();

    const int d = dh * 128 + tid;
    const float* tb = t + ((long)b * M144) * DIM + d;

    // contraction: x[h] and x[12+w] accumulate a*t over the 12x12 grid
    float x[24];
#pragma unroll
    for (int i = 0; i < 24; i++) x[i] = 0.f;

#pragma unroll
    for (int h = 0; h < S0; h++) {
#pragma unroll
        for (int w = 0; w < S0; w++) {
            const int r = h * S0 + w;
            float v = adjc[r] * tb[(long)r * DIM];
            x[h]      += v;
            x[12 + w] += v;
        }
    }

    // fc1: i-outer / j-inner, 48 independent accumulators (full FMA ILP)
    float a[48];
#pragma unroll
    for (int j = 0; j < 48; j++) a[j] = b1s[j];

#pragma unroll
    for (int i = 0; i < 24; i++) {
        const float xv = x[i];
        const float4* wr = (const float4*)&w1i[i][0];
#pragma unroll
        for (int j4 = 0; j4 < 12; j4++) {
            float4 w = wr[j4];
            a[j4 * 4 + 0] += xv * w.x;
            a[j4 * 4 + 1] += xv * w.y;
            a[j4 * 4 + 2] += xv * w.z;
            a[j4 * 4 + 3] += xv * w.w;
        }
    }

    // gelu + fc2 dot: 48 independent gelus, 4 interleaved output chains
    float o0 = 0.f, o1 = 0.f, o2 = 0.f, o3 = 0.f;
#pragma unroll
    for (int j = 0; j < 48; j += 4) {
        o0 += gelu_exact(a[j + 0]) * w2s[j + 0];
        o1 += gelu_exact(a[j + 1]) * w2s[j + 1];
        o2 += gelu_exact(a[j + 2]) * w2s[j + 2];
        o3 += gelu_exact(a[j + 3]) * w2s[j + 3];
    }
    g_fus[((long)(b * NP) + p) * DIM + d] = ((b2[0] + o0) + o1) + (o2 + o3);
}

// ---------------- U = softmax(fc2_na) @ fus + t, softmax fused ----------------
__global__ __launch_bounds__(128)
void u_softmax_gemm(const float* __restrict__ na_b2,
                    const float* __restrict__ t)
{
#if __CUDA_ARCH__ >= 900
    cudaGridDependencySynchronize();
#endif
    __shared__ float As[NP][17];        // softmaxed attn, [k][row]
    __shared__ __align__(16) float Bs[NP][68];   // fus panel [k][col]

    const int cb  = blockIdx.x;
    const int rb  = blockIdx.y;
    const int b   = blockIdx.z;
    const int tid = threadIdx.x;
    const int row0 = rb * 16;
    const int col0 = cb * 64;

    {
        const float* fb = g_fus + ((long)b * NP) * DIM + col0;
        for (int idx = tid; idx < NP * 16; idx += 128) {
            int k = idx >> 4, c4 = (idx & 15) * 4;
            float4 v = *(const float4*)&fb[(long)k * DIM + c4];
            *(float4*)&Bs[k][c4] = v;
        }
    }

    {
        const int lr  = tid >> 3;
        const int sub = tid & 7;
        const long rbase = ((long)(b * M144) + row0 + lr) * NP;
        float v[16];
        float mx = -1e30f;
#pragma unroll
        for (int i = 0; i < 16; i++) {
            int k = sub * 16 + i;
            v[i] = g_pattn[rbase + k] + g_pattn[(long)MT * NP + rbase + k] + na_b2[k];
            mx = fmaxf(mx, v[i]);
        }
#pragma unroll
        for (int o = 1; o < 8; o <<= 1) mx = fmaxf(mx, __shfl_xor_sync(0xffffffffu, mx, o));
        float sum = 0.f;
#pragma unroll
        for (int i = 0; i < 16; i++) { v[i] = expf(v[i] - mx); sum += v[i]; }
#pragma unroll
        for (int o = 1; o < 8; o <<= 1) sum += __shfl_xor_sync(0xffffffffu, sum, o);
        float inv = 1.f / sum;
#pragma unroll
        for (int i = 0; i < 16; i++) As[sub * 16 + i][lr] = v[i] * inv;
    }
    __syncthreads();

    const int tm = tid >> 4;
    const int tn = tid & 15;
    const int m0 = tm * 2;
    const int n0 = tn * 4;

    float acc[2][4];
#pragma unroll
    for (int i = 0; i < 2; i++)
#pragma unroll
        for (int j = 0; j < 4; j++) acc[i][j] = 0.f;

#pragma unroll 8
    for (int k = 0; k < NP; k++) {
        float a0 = As[k][m0], a1 = As[k][m0 + 1];
        float4 bb = *(const float4*)&Bs[k][n0];
        acc[0][0] += a0 * bb.x; acc[0][1] += a0 * bb.y;
        acc[0][2] += a0 * bb.z; acc[0][3] += a0 * bb.w;
        acc[1][0] += a1 * bb.x; acc[1][1] += a1 * bb.y;
        acc[1][2] += a1 * bb.z; acc[1][3] += a1 * bb.w;
    }

#pragma unroll
    for (int i = 0; i < 2; i++) {
        const int row = row0 + m0 + i;
        const float4 r = *(const float4*)&t[((long)(b * M144) + row) * DIM + col0 + n0];
        float4 v;
        v.x = acc[i][0] + r.x; v.y = acc[i][1] + r.y;
        v.z = acc[i][2] + r.z; v.w = acc[i][3] + r.w;
        *(float4*)&g_U[((long)(b * M144) + row) * DIM + col0 + n0] = v;
    }
}

// ---------------- final scatter-broadcast of the 144 unique rows --------------
__global__ __launch_bounds__(256)
void scatter_kernel(float4* __restrict__ out) {
#if __CUDA_ARCH__ >= 900
    cudaGridDependencySynchronize();
#endif
    const int wq = threadIdx.x >> 6;
    const int dq = threadIdx.x & 63;
    const int w  = blockIdx.x * 4 + wq;
    const int h  = blockIdx.y;
    const int b  = blockIdx.z;
    const int r  = (h / 10) * S0 + (3 * w) / 40;
    const float4* src = reinterpret_cast<const float4*>(g_U)
                        + (long)(b * M144 + r) * (DIM / 4);
    float4* dst = out + (long)(((b * H_) + h) * W_ + w) * (DIM / 4);
    dst[dq] = src[dq];
}

// ---------------- PDL launch helper -------------------------------------------
template<typename K, typename... A>
static void launch_pdl(dim3 g, dim3 blk, K kern, A... args) {
    cudaLaunchConfig_t cfg = {};
    cfg.gridDim = g;
    cfg.blockDim = blk;
    cfg.dynamicSmemBytes = 0;
    cfg.stream = 0;
    cudaLaunchAttribute at;
    at.id = cudaLaunchAttributeProgrammaticStreamSerialization;
    at.val.programmaticStreamSerializationAllowed = 1;
    cfg.attrs = &at;
    cfg.numAttrs = 1;
    cudaLaunchKernelEx(&cfg, kern, args...);
}

// ==============================================================================
extern "C" void kernel_launch(void* const* d_in, const int* in_sizes, int n_in,
                              void* d_out, int out_size) {
    const float* token_init  = (const float*)d_in[0];   // [4,12,12,256] == compact t
    const float* point_token = (const float*)d_in[1];
    const float* nr_w1 = (const float*)d_in[2];
    const float* nr_b1 = (const float*)d_in[3];
    const float* nr_w2 = (const float*)d_in[4];
    const float* nr_b2 = (const float*)d_in[5];
    const float* na_w1 = (const float*)d_in[6];
    const float* na_b1 = (const float*)d_in[7];
    const float* na_w2 = (const float*)d_in[8];
    const float* na_b2 = (const float*)d_in[9];
    const float* tf_w1 = (const float*)d_in[10];
    const float* tf_b1 = (const float*)d_in[11];
    const float* tf_w2 = (const float*)d_in[12];
    const float* tf_b2 = (const float*)d_in[13];
    float* out = (float*)d_out;

    float *A0_p, *H_p, *padj_p, *pattn_p;
    cudaGetSymbolAddress((void**)&A0_p,   g_A0);
    cudaGetSymbolAddress((void**)&H_p,    g_H);
    cudaGetSymbolAddress((void**)&padj_p, g_padj);
    cudaGetSymbolAddress((void**)&pattn_p,g_pattn);

    const float scale = 0.0625f;                    // dim^-0.5
    const float rs2   = 2.f * 0.20412414523193154f; // 2 * 24^-0.5

    // 1. A0 = t144 @ P^T * scale   [4*144,128]
    launch_pdl(dim3(NP / 32, M144 / 16, B_), dim3(64),
        gemm_f32<16, 32, 16, 2, 4, true, false, false, false, false, 1>,
        token_init, point_token, (const float*)nullptr,
        (const float*)nullptr, (const float*)nullptr, (const float*)nullptr,
        A0_p, (float*)nullptr,
        (int)DIM, scale,
        (long)M144 * DIM, (int)DIM, 0,
        (long)NP * DIM, (int)DIM,
        (long)M144 * NP, (int)NP, 0,
        (long)0, 0, (long)0);

    // 2. fc1 (nr & na): H = gelu(A0 @ w1 + b1)   [576,1024]
    launch_pdl(dim3(HID / 64, MT / 32, 2), dim3(128),
        gemm_f32<32, 64, 16, 4, 4, false, true, true, false, true, 1>,
        (const float*)A0_p, nr_w1, na_w1, nr_b1, na_b1, (const float*)nullptr,
        H_p, H_p,
        (int)NP, 1.f,
        (long)0, (int)NP, 0,
        (long)0, (int)HID,
        (long)0, (int)(2 * HID), (int)HID,
        (long)0, 0, (long)0);

    // 3. fc2 split-K2 (nr & na): raw partials (bias added by consumers)
    launch_pdl(dim3(NP / 32, MT / 32, 4), dim3(128),
        gemm_f32<32, 32, 16, 4, 2, false, false, false, false, true, 2>,
        (const float*)H_p, nr_w2, na_w2,
        (const float*)nullptr, (const float*)nullptr, (const float*)nullptr,
        padj_p, pattn_p,
        (int)HID, 1.f,
        (long)0, (int)(2 * HID), (int)HID,
        (long)0, (int)NP,
        (long)0, (int)NP, 0,
        (long)0, 0, (long)MT * NP);

    // 4. fused node contraction + token_fused MLP (ILP-restructured, d-split)
    launch_pdl(dim3(NP, B_, 2), dim3(128),
        node_tf_fused,
        token_init, nr_b2, tf_w1, tf_b1, tf_w2, tf_b2, rs2);

    // 5. U = softmax(na partials + bias) @ fus + t144   [4*144,256]
    launch_pdl(dim3(DIM / 64, M144 / 16, B_), dim3(128),
        u_softmax_gemm, na_b2, token_init);

    // 6. broadcast unique rows to the full [4,19200,256] output
    launch_pdl(dim3(W_ / 4, H_, B_), dim3(256),
        scatter_kernel, (float4*)out);
}